// round 12
// baseline (speedup 1.0000x reference)
#include <cuda_runtime.h>
#include <cuda_fp16.h>
#include <mma.h>

using namespace nvcuda;

#define NN 100000
#define NE 1600000
#define NF 64
#define NC 32
#define OS_LD 68   // float smem epilogue row stride

// ---------------- scratch (static device memory) --------------------------
__device__ __align__(256) __half2 g_x16[NN * (NF / 2)];   // fp16(x) (UNSCALED)
__device__ __align__(256) __half2 g_h1[NN * (NF / 2)];    // layer-1 output (fp16)
__device__ __align__(256) __half2 g_t3[NN * (NC / 2)];    // W3-transformed h2 (fp16)
__device__ int   g_deg_out[NN];            // zero-init; re-zeroed inside scan1
__device__ int   g_deg_in[NN];             // re-zeroed inside scan3
__device__ float g_norm_out[NN];
__device__ float g_norm_in[NN];
__device__ int   g_row_ptr[NN + 1];
__device__ int   g_partials[64];
__device__ __align__(256) int g_edge_src[NE];
__device__ __align__(256) int g_rank[NE];   // within-dst-segment rank of each edge

// ---------------- xconv: g_x16 = fp16(x)  (no deps — runs on side stream) --
__global__ void k_xconv(const float* __restrict__ x) {
    int i = blockIdx.x * blockDim.x + threadIdx.x;   // over NN*16 float4
    if (i < NN * (NF / 4)) {
        float4 v = ((const float4*)x)[i];
        g_x16[i * 2]     = __floats2half2_rn(v.x, v.y);
        g_x16[i * 2 + 1] = __floats2half2_rn(v.z, v.w);
    }
}

// ---------------- out-degree histogram (half of edges per kernel) ---------
__global__ void k_hist_out(const int4* __restrict__ src4, int base4) {
    int i = blockIdx.x * blockDim.x + threadIdx.x;
    if (i < NE / 8) {
        int4 s = src4[base4 + i];
        atomicAdd(&g_deg_out[s.x], 1); atomicAdd(&g_deg_out[s.y], 1);
        atomicAdd(&g_deg_out[s.z], 1); atomicAdd(&g_deg_out[s.w], 1);
    }
}

// ---------------- in-degree histogram + rank capture (THE suspect) --------
__global__ void k_hist_in(const int4* __restrict__ dst4, int4* __restrict__ rank4) {
    int i = blockIdx.x * blockDim.x + threadIdx.x;
    if (i < NE / 4) {
        int4 d = dst4[i];
        int4 r;
        r.x = atomicAdd(&g_deg_in[d.x], 1);
        r.y = atomicAdd(&g_deg_in[d.y], 1);
        r.z = atomicAdd(&g_deg_in[d.z], 1);
        r.w = atomicAdd(&g_deg_in[d.w], 1);
        rank4[i] = r;
    }
}

// ---------------- scan pass 1: norms + block sums + deg_out re-zero -------
#define SCAN_T 512
#define SCAN_I 4
#define SCAN_CHUNK (SCAN_T * SCAN_I)                     // 2048
#define SCAN_NB ((NN + SCAN_CHUNK - 1) / SCAN_CHUNK)     // 49

__global__ __launch_bounds__(SCAN_T) void k_scan1() {
    __shared__ int sm[SCAN_T];
    int tid = threadIdx.x;
    int base = blockIdx.x * SCAN_CHUNK + tid * SCAN_I;
    int s = 0;
#pragma unroll
    for (int j = 0; j < SCAN_I; j++) {
        int i = base + j;
        if (i < NN) {
            int di = g_deg_in[i];
            s += di;
            g_norm_in[i]  = rsqrtf((float)max(di, 1));
            g_norm_out[i] = rsqrtf((float)max(g_deg_out[i], 1));
            g_deg_out[i] = 0;                  // restore for next replay
        }
    }
    sm[tid] = s;
    __syncthreads();
    for (int off = SCAN_T / 2; off > 0; off >>= 1) {
        if (tid < off) sm[tid] += sm[tid + off];
        __syncthreads();
    }
    if (tid == 0) g_partials[blockIdx.x] = sm[0];
}

// ---------------- scan pass 2 (fused): partial-prefix + row_ptr + rezero --
__global__ __launch_bounds__(SCAN_T) void k_scan3() {
    __shared__ int sm[SCAN_T];
    __shared__ int pp[SCAN_NB];
    int tid = threadIdx.x;
    if (tid == 0) {
        int run = 0;
#pragma unroll
        for (int b = 0; b < SCAN_NB; b++) { pp[b] = run; run += g_partials[b]; }
        if (blockIdx.x == 0) g_row_ptr[NN] = NE;
    }
    int base = blockIdx.x * SCAN_CHUNK + tid * SCAN_I;
    int c[SCAN_I];
    int s = 0;
#pragma unroll
    for (int j = 0; j < SCAN_I; j++) {
        int i = base + j;
        c[j] = (i < NN) ? g_deg_in[i] : 0;
        if (i < NN) g_deg_in[i] = 0;           // restore for next replay
        s += c[j];
    }
    sm[tid] = s;
    __syncthreads();
    for (int off = 1; off < SCAN_T; off <<= 1) {
        int v = (tid >= off) ? sm[tid - off] : 0;
        __syncthreads();
        sm[tid] += v;
        __syncthreads();
    }
    int excl = sm[tid] - s + pp[blockIdx.x];
#pragma unroll
    for (int j = 0; j < SCAN_I; j++) {
        int i = base + j;
        if (i < NN) g_row_ptr[i] = excl;
        excl += c[j];
    }
}

// ---------------- scatter (atomic-free: row_ptr[dst] + rank) --------------
__global__ void k_scatter(const int4* __restrict__ src4, const int4* __restrict__ dst4,
                          const int4* __restrict__ rank4) {
    int i = blockIdx.x * blockDim.x + threadIdx.x;
    if (i < NE / 4) {
        int4 s = src4[i];
        int4 d = dst4[i];
        int4 r = rank4[i];
        g_edge_src[g_row_ptr[d.x] + r.x] = s.x;
        g_edge_src[g_row_ptr[d.y] + r.y] = s.y;
        g_edge_src[g_row_ptr[d.z] + r.z] = s.z;
        g_edge_src[g_row_ptr[d.w] + r.w] = s.w;
    }
}

// ---------------- gather-aggregates ---------------------------------------
__device__ __forceinline__ void acc_u4(const uint4& v, float acc[8]) {
    float2 f;
    f = __half22float2(*(const __half2*)&v.x); acc[0] += f.x; acc[1] += f.y;
    f = __half22float2(*(const __half2*)&v.y); acc[2] += f.x; acc[3] += f.y;
    f = __half22float2(*(const __half2*)&v.z); acc[4] += f.x; acc[5] += f.y;
    f = __half22float2(*(const __half2*)&v.w); acc[6] += f.x; acc[7] += f.y;
}

// scaled variant: acc += n * v   (per-edge norm_out fold, layer1 only)
__device__ __forceinline__ void acc_u4s(const uint4& v, float n, float acc[8]) {
    float2 f;
    f = __half22float2(*(const __half2*)&v.x); acc[0] = fmaf(n, f.x, acc[0]); acc[1] = fmaf(n, f.y, acc[1]);
    f = __half22float2(*(const __half2*)&v.y); acc[2] = fmaf(n, f.x, acc[2]); acc[3] = fmaf(n, f.y, acc[3]);
    f = __half22float2(*(const __half2*)&v.z); acc[4] = fmaf(n, f.x, acc[4]); acc[5] = fmaf(n, f.y, acc[5]);
    f = __half22float2(*(const __half2*)&v.w); acc[6] = fmaf(n, f.x, acc[6]); acc[7] = fmaf(n, f.y, acc[7]);
}

// layer1 agg: gathers UNSCALED x16 and applies norm_out[src] per edge.
__device__ __forceinline__ void agg64_scaled(const __half* __restrict__ inh,
                                             int beg, int end, int sub, int fc,
                                             float acc[8]) {
#pragma unroll
    for (int q = 0; q < 8; q++) acc[q] = 0.f;
    int e = beg;
    for (; e + 15 < end; e += 16) {
        int i0 = g_edge_src[e + sub];
        int i1 = g_edge_src[e + 4 + sub];
        int i2 = g_edge_src[e + 8 + sub];
        int i3 = g_edge_src[e + 12 + sub];
        float n0 = g_norm_out[i0], n1 = g_norm_out[i1];
        float n2 = g_norm_out[i2], n3 = g_norm_out[i3];
        uint4 a = *(const uint4*)&inh[i0 * NF + fc];
        uint4 b = *(const uint4*)&inh[i1 * NF + fc];
        uint4 c = *(const uint4*)&inh[i2 * NF + fc];
        uint4 d = *(const uint4*)&inh[i3 * NF + fc];
        acc_u4s(a, n0, acc); acc_u4s(b, n1, acc);
        acc_u4s(c, n2, acc); acc_u4s(d, n3, acc);
    }
    for (; e + 7 < end; e += 8) {
        int i0 = g_edge_src[e + sub];
        int i1 = g_edge_src[e + 4 + sub];
        float n0 = g_norm_out[i0], n1 = g_norm_out[i1];
        uint4 a = *(const uint4*)&inh[i0 * NF + fc];
        uint4 b = *(const uint4*)&inh[i1 * NF + fc];
        acc_u4s(a, n0, acc); acc_u4s(b, n1, acc);
    }
    for (; e < end; e += 4) {
        int eid = e + sub;
        uint4 v = make_uint4(0u, 0u, 0u, 0u);
        float n = 0.f;
        if (eid < end) {
            int s = g_edge_src[eid];
            n = g_norm_out[s];
            v = *(const uint4*)&inh[s * NF + fc];
        }
        acc_u4s(v, n, acc);
    }
#pragma unroll
    for (int q = 0; q < 8; q++) {
        acc[q] += __shfl_xor_sync(0xffffffffu, acc[q], 8);
        acc[q] += __shfl_xor_sync(0xffffffffu, acc[q], 16);
    }
}

// plain agg (layer2; inputs pre-scaled in epilogue)
__device__ __forceinline__ void agg64_node(const __half* __restrict__ inh,
                                           int beg, int end, int sub, int fc,
                                           float acc[8]) {
#pragma unroll
    for (int q = 0; q < 8; q++) acc[q] = 0.f;
    int e = beg;
    for (; e + 15 < end; e += 16) {
        int i0 = g_edge_src[e + sub];
        int i1 = g_edge_src[e + 4 + sub];
        int i2 = g_edge_src[e + 8 + sub];
        int i3 = g_edge_src[e + 12 + sub];
        uint4 a = *(const uint4*)&inh[i0 * NF + fc];
        uint4 b = *(const uint4*)&inh[i1 * NF + fc];
        uint4 c = *(const uint4*)&inh[i2 * NF + fc];
        uint4 d = *(const uint4*)&inh[i3 * NF + fc];
        acc_u4(a, acc); acc_u4(b, acc); acc_u4(c, acc); acc_u4(d, acc);
    }
    for (; e + 7 < end; e += 8) {
        int i0 = g_edge_src[e + sub];
        int i1 = g_edge_src[e + 4 + sub];
        uint4 a = *(const uint4*)&inh[i0 * NF + fc];
        uint4 b = *(const uint4*)&inh[i1 * NF + fc];
        acc_u4(a, acc); acc_u4(b, acc);
    }
    for (; e < end; e += 4) {
        int eid = e + sub;
        uint4 v = make_uint4(0u, 0u, 0u, 0u);
        if (eid < end) {
            int s = g_edge_src[eid];
            v = *(const uint4*)&inh[s * NF + fc];
        }
        acc_u4(v, acc);
    }
#pragma unroll
    for (int q = 0; q < 8; q++) {
        acc[q] += __shfl_xor_sync(0xffffffffu, acc[q], 8);
        acc[q] += __shfl_xor_sync(0xffffffffu, acc[q], 16);
    }
}

// ---------------- fused layer 1: scaled agg + wmma GEMM + epilogue --------
__global__ __launch_bounds__(256) void k_layer1(const float* __restrict__ W1,
                                                const float* __restrict__ b1) {
    __shared__ __align__(16) __half Wh[NF * NF];
    __shared__ __align__(16) __half Ah[32][NF];
    __shared__ __align__(16) float  Os[32][OS_LD];
    int tid = threadIdx.x;
    int row0 = blockIdx.x * 32;
    for (int i = tid; i < NF * NF; i += 256) Wh[i] = __float2half(W1[i]);

    const __half* inh = (const __half*)g_x16;
    int wid = tid >> 5, lane = tid & 31;
    int sub = lane >> 3;
    int fc  = (lane & 7) * 8;
#pragma unroll
    for (int j = 0; j < 4; j++) {
        int nl = (wid << 2) + j;
        int node = row0 + nl;
        float acc[8];
        agg64_scaled(inh, g_row_ptr[node], g_row_ptr[node + 1], sub, fc, acc);
        if (lane < 8) {
            float ni = g_norm_in[node];
#pragma unroll
            for (int q = 0; q < 8; q++) Ah[nl][fc + q] = __float2half(acc[q] * ni);
        }
    }
    __syncthreads();

    {
        int mt = wid >> 2, nt = wid & 3;
        wmma::fragment<wmma::accumulator, 16, 16, 16, float> fC;
        wmma::fill_fragment(fC, 0.f);
#pragma unroll
        for (int k = 0; k < 4; k++) {
            wmma::fragment<wmma::matrix_a, 16, 16, 16, __half, wmma::row_major> fA;
            wmma::fragment<wmma::matrix_b, 16, 16, 16, __half, wmma::row_major> fB;
            wmma::load_matrix_sync(fA, &Ah[mt * 16][k * 16], NF);
            wmma::load_matrix_sync(fB, &Wh[(k * 16) * NF + nt * 16], NF);
            wmma::mma_sync(fC, fA, fB, fC);
        }
        wmma::store_matrix_sync(&Os[mt * 16][nt * 16], fC, OS_LD, wmma::mem_row_major);
    }
    __syncthreads();

    int er = tid >> 3;
    int ec = (tid & 7) * 8;
    int g = row0 + er;
    float so = g_norm_out[g];
#pragma unroll
    for (int q = 0; q < 8; q += 2) {
        float o0 = fmaxf(Os[er][ec + q]     + b1[ec + q],     0.f) * so;
        float o1 = fmaxf(Os[er][ec + q + 1] + b1[ec + q + 1], 0.f) * so;
        g_h1[g * 32 + ((ec + q) >> 1)] = __floats2half2_rn(o0, o1);
    }
}

// layer 2 + fused W3: t3 = (relu(aggW2+b2)*norm_out) @ W3 ------------------
__global__ __launch_bounds__(256) void k_layer2(const float* __restrict__ W2,
                                                const float* __restrict__ b2,
                                                const float* __restrict__ W3) {
    __shared__ __align__(16) __half Wh[NF * NF];
    __shared__ __align__(16) __half W3h[NF * NC];
    __shared__ __align__(16) __half Ah[32][NF];
    __shared__ __align__(16) float  Os[32][OS_LD];
    int tid = threadIdx.x;
    int row0 = blockIdx.x * 32;
    for (int i = tid; i < NF * NF; i += 256) Wh[i] = __float2half(W2[i]);
    for (int i = tid; i < NF * NC; i += 256) W3h[i] = __float2half(W3[i]);

    const __half* inh = (const __half*)g_h1;
    int wid = tid >> 5, lane = tid & 31;
    int sub = lane >> 3;
    int fc  = (lane & 7) * 8;
#pragma unroll
    for (int j = 0; j < 4; j++) {
        int nl = (wid << 2) + j;
        int node = row0 + nl;
        float acc[8];
        agg64_node(inh, g_row_ptr[node], g_row_ptr[node + 1], sub, fc, acc);
        if (lane < 8) {
            float ni = g_norm_in[node];
#pragma unroll
            for (int q = 0; q < 8; q++) Ah[nl][fc + q] = __float2half(acc[q] * ni);
        }
    }
    __syncthreads();

    {
        int mt = wid >> 2, nt = wid & 3;
        wmma::fragment<wmma::accumulator, 16, 16, 16, float> fC;
        wmma::fill_fragment(fC, 0.f);
#pragma unroll
        for (int k = 0; k < 4; k++) {
            wmma::fragment<wmma::matrix_a, 16, 16, 16, __half, wmma::row_major> fA;
            wmma::fragment<wmma::matrix_b, 16, 16, 16, __half, wmma::row_major> fB;
            wmma::load_matrix_sync(fA, &Ah[mt * 16][k * 16], NF);
            wmma::load_matrix_sync(fB, &Wh[(k * 16) * NF + nt * 16], NF);
            wmma::mma_sync(fC, fA, fB, fC);
        }
        wmma::store_matrix_sync(&Os[mt * 16][nt * 16], fC, OS_LD, wmma::mem_row_major);
    }
    __syncthreads();

    {
        int er = tid >> 3;
        int ec = (tid & 7) * 8;
        float so = g_norm_out[row0 + er];
#pragma unroll
        for (int q = 0; q < 8; q++)
            Ah[er][ec + q] = __float2half(fmaxf(Os[er][ec + q] + b2[ec + q], 0.f) * so);
    }
    __syncthreads();

    if (wid < 4) {
        int mt = wid >> 1, nt = wid & 1;
        wmma::fragment<wmma::accumulator, 16, 16, 16, float> fC;
        wmma::fill_fragment(fC, 0.f);
#pragma unroll
        for (int k = 0; k < 4; k++) {
            wmma::fragment<wmma::matrix_a, 16, 16, 16, __half, wmma::row_major> fA;
            wmma::fragment<wmma::matrix_b, 16, 16, 16, __half, wmma::row_major> fB;
            wmma::load_matrix_sync(fA, &Ah[mt * 16][k * 16], NF);
            wmma::load_matrix_sync(fB, &W3h[(k * 16) * NC + nt * 16], NC);
            wmma::mma_sync(fC, fA, fB, fC);
        }
        wmma::store_matrix_sync(&Os[mt * 16][nt * 16], fC, OS_LD, wmma::mem_row_major);
    }
    __syncthreads();

    {
        int er = tid >> 3;
        int ec = (tid & 7) * 4;
        int g = row0 + er;
        g_t3[g * 16 + (ec >> 1)]     = __floats2half2_rn(Os[er][ec],     Os[er][ec + 1]);
        g_t3[g * 16 + (ec >> 1) + 1] = __floats2half2_rn(Os[er][ec + 2], Os[er][ec + 3]);
    }
}

// ---------------- final: out = norm_in * Agg(t3) + b3 ---------------------
__global__ void k_out(const float* __restrict__ b3, float* __restrict__ out) {
    int gt = blockIdx.x * blockDim.x + threadIdx.x;
    int w = gt >> 5, lane = gt & 31;
    int sub = lane >> 3;
    int fc  = (lane & 7) * 4;
    const __half* t3 = (const __half*)g_t3;
    int beg = g_row_ptr[w], end = g_row_ptr[w + 1];
    float acc[4] = {};
    int e = beg;
    for (; e + 15 < end; e += 16) {
        int i0 = g_edge_src[e + sub];
        int i1 = g_edge_src[e + 4 + sub];
        int i2 = g_edge_src[e + 8 + sub];
        int i3 = g_edge_src[e + 12 + sub];
        uint2 a = *(const uint2*)&t3[i0 * NC + fc];
        uint2 b = *(const uint2*)&t3[i1 * NC + fc];
        uint2 c = *(const uint2*)&t3[i2 * NC + fc];
        uint2 d = *(const uint2*)&t3[i3 * NC + fc];
        float2 f;
        f = __half22float2(*(const __half2*)&a.x); acc[0] += f.x; acc[1] += f.y;
        f = __half22float2(*(const __half2*)&a.y); acc[2] += f.x; acc[3] += f.y;
        f = __half22float2(*(const __half2*)&b.x); acc[0] += f.x; acc[1] += f.y;
        f = __half22float2(*(const __half2*)&b.y); acc[2] += f.x; acc[3] += f.y;
        f = __half22float2(*(const __half2*)&c.x); acc[0] += f.x; acc[1] += f.y;
        f = __half22float2(*(const __half2*)&c.y); acc[2] += f.x; acc[3] += f.y;
        f = __half22float2(*(const __half2*)&d.x); acc[0] += f.x; acc[1] += f.y;
        f = __half22float2(*(const __half2*)&d.y); acc[2] += f.x; acc[3] += f.y;
    }
    for (; e + 7 < end; e += 8) {
        int i0 = g_edge_src[e + sub];
        int i1 = g_edge_src[e + 4 + sub];
        uint2 a = *(const uint2*)&t3[i0 * NC + fc];
        uint2 b = *(const uint2*)&t3[i1 * NC + fc];
        float2 f;
        f = __half22float2(*(const __half2*)&a.x); acc[0] += f.x; acc[1] += f.y;
        f = __half22float2(*(const __half2*)&a.y); acc[2] += f.x; acc[3] += f.y;
        f = __half22float2(*(const __half2*)&b.x); acc[0] += f.x; acc[1] += f.y;
        f = __half22float2(*(const __half2*)&b.y); acc[2] += f.x; acc[3] += f.y;
    }
    for (; e < end; e += 4) {
        int eid = e + sub;
        uint2 v = make_uint2(0u, 0u);
        if (eid < end) {
            int s = g_edge_src[eid];
            v = *(const uint2*)&t3[s * NC + fc];
        }
        float2 f;
        f = __half22float2(*(const __half2*)&v.x); acc[0] += f.x; acc[1] += f.y;
        f = __half22float2(*(const __half2*)&v.y); acc[2] += f.x; acc[3] += f.y;
    }
#pragma unroll
    for (int q = 0; q < 4; q++) {
        acc[q] += __shfl_xor_sync(0xffffffffu, acc[q], 8);
        acc[q] += __shfl_xor_sync(0xffffffffu, acc[q], 16);
    }
    if (lane < 8) {
        float ni = g_norm_in[w];
        float4 bb = *(const float4*)&b3[fc];
        float4 o;
        o.x = acc[0] * ni + bb.x;
        o.y = acc[1] * ni + bb.y;
        o.z = acc[2] * ni + bb.z;
        o.w = acc[3] * ni + bb.w;
        *(float4*)&out[w * NC + fc] = o;
    }
}

// ---------------- launch -------------------------------------------------
extern "C" void kernel_launch(void* const* d_in, const int* in_sizes, int n_in,
                              void* d_out, int out_size) {
    const float* x   = (const float*)d_in[0];
    const int*   src = (const int*)d_in[1];
    const int*   dst = (const int*)d_in[2];
    const float* W1  = (const float*)d_in[3];
    const float* b1  = (const float*)d_in[4];
    const float* W2  = (const float*)d_in[5];
    const float* b2  = (const float*)d_in[6];
    const float* W3  = (const float*)d_in[7];
    const float* b3  = (const float*)d_in[8];
    float* out = (float*)d_out;

    static cudaStream_t s2 = nullptr;
    static cudaEvent_t evA = nullptr, evB = nullptr;
    static int* p_rank = nullptr;
    if (s2 == nullptr) {
        cudaStreamCreateWithFlags(&s2, cudaStreamNonBlocking);
        cudaEventCreateWithFlags(&evA, cudaEventDisableTiming);
        cudaEventCreateWithFlags(&evB, cudaEventDisableTiming);
        cudaGetSymbolAddress((void**)&p_rank, g_rank);
    }

    const int NB_EDGE4 = (NE / 4 + 255) / 256;          // 1563
    const int NB_EDGE8 = (NE / 8 + 255) / 256;          // 782
    const int NB_X     = (NN * (NF / 4) + 255) / 256;   // 6250
    const int NB_OUT   = NN * 32 / 256;                 // 12500

    // fork: xconv (dep-free) on s2, concurrent with the atomic hist stage
    cudaEventRecord(evA, 0);
    cudaStreamWaitEvent(s2, evA, 0);
    k_xconv<<<NB_X, 256, 0, s2>>>(x);                           // kernel #1
    cudaEventRecord(evB, s2);

    k_hist_out<<<NB_EDGE8, 256>>>((const int4*)src, 0);         // #2
    k_hist_out<<<NB_EDGE8, 256>>>((const int4*)src, NE / 8);    // #3
    k_hist_in<<<NB_EDGE4, 256>>>((const int4*)dst, (int4*)p_rank); // #4 <- profiled
    k_scan1<<<SCAN_NB, SCAN_T>>>();
    k_scan3<<<SCAN_NB, SCAN_T>>>();
    k_scatter<<<NB_EDGE4, 256>>>((const int4*)src, (const int4*)dst, (const int4*)p_rank);

    cudaStreamWaitEvent(0, evB, 0);   // join: layer1 needs g_x16
    k_layer1<<<NN / 32, 256>>>(W1, b1);
    k_layer2<<<NN / 32, 256>>>(W2, b2, W3);
    k_out<<<NB_OUT, 256>>>(b3, out);
}